// round 15
// baseline (speedup 1.0000x reference)
#include <cuda_runtime.h>
#include <cuda_fp16.h>
#include <cstdint>

// ---------------------------------------------------------------------------
// Shapes: N0 = N1 = 50000, D0 = 256, D1 = 512, DO = 256, E = 1600000
// ---------------------------------------------------------------------------
#define MAX_N   50000
#define MAX_E   1600000
#define DO_DIM  256
#define LN_EPS  1e-5f

// ---------------------------------------------------------------------------
// Device scratch (static — no allocations allowed)
// ---------------------------------------------------------------------------
__device__ __align__(16) __half g_hproj0[MAX_N * DO_DIM];
__device__ __align__(16) __half g_hproj1[MAX_N * DO_DIM];
__device__ __align__(16) float  g_res1  [MAX_N * DO_DIM];

__device__ int   g_cnt0[MAX_N],  g_cnt1[MAX_N];
__device__ int   g_off0[MAX_N],  g_off1[MAX_N];
__device__ int   g_cur0[MAX_N],  g_cur1[MAX_N];
__device__ int   g_bsum[2 * 256];
__device__ int2  g_edge0[MAX_E], g_edge1[MAX_E];

// W transposed fp16: [N=256][K] row-major
__device__ __align__(16) __half g_w0[256 * 256];
__device__ __align__(16) __half g_w1[256 * 512];
__device__ __align__(16) __half g_wr[256 * 512];

// ---------------------------------------------------------------------------
// PTX helpers (compute_103-safe)
// ---------------------------------------------------------------------------
__device__ __forceinline__ uint32_t smem_u32(const void* p) {
    uint32_t a;
    asm("{ .reg .u64 t; cvta.to.shared.u64 t, %1; cvt.u32.u64 %0, t; }"
        : "=r"(a) : "l"(p));
    return a;
}

#define LDSM_X4(r0, r1, r2, r3, addr)                                        \
    asm volatile("ldmatrix.sync.aligned.m8n8.x4.shared.b16 {%0,%1,%2,%3}, [%4];" \
        : "=r"(r0), "=r"(r1), "=r"(r2), "=r"(r3) : "r"(addr))

#define MMA_F16(d, a0, a1, a2, a3, b0, b1)                                   \
    asm volatile("mma.sync.aligned.m16n8k16.row.col.f32.f16.f16.f32 "        \
        "{%0,%1,%2,%3},{%4,%5,%6,%7},{%8,%9},{%0,%1,%2,%3};"                 \
        : "+f"((d)[0]), "+f"((d)[1]), "+f"((d)[2]), "+f"((d)[3])             \
        : "r"(a0), "r"(a1), "r"(a2), "r"(a3), "r"(b0), "r"(b1))

// ---------------------------------------------------------------------------
// 512-thread GEMM body. Block tile 128(M) x 128(N), K-chunk 32,
// double-buffered smem, 16 warps @ 32x32 warp tiles.
//   C0 (fp16) = A @ B0^T ; [NB==2] C1 (fp32) = A @ B1^T
// Stage bytes: A [0,10240) ; B[jj] at 10240 + jj*10240
// ---------------------------------------------------------------------------
template <int NB>
__device__ __forceinline__
void gemm_body512(const float* __restrict__ A,
                  const __half* __restrict__ B0,
                  const __half* __restrict__ B1,
                  __half* __restrict__ C0, float* __restrict__ C1,
                  int M, int K, int bx, int by, char* smem)
{
    constexpr int APAD  = 40;
    constexpr int STAGE = 10240 * (1 + NB);

    const int tid  = threadIdx.x;
    const int lane = tid & 31;
    const int wid  = tid >> 5;           // 0..15
    const int wm   = wid >> 2;           // 0..3 (M)
    const int wn   = wid & 3;            // 0..3 (N)
    const int row0 = by * 128;
    const int col0 = bx * 128;

    const int NC = K >> 5;
    const __half* Bp[2] = {B0, B1};

    float acc[NB][2][4][4];
    #pragma unroll
    for (int jj = 0; jj < NB; jj++)
        #pragma unroll
        for (int i = 0; i < 2; i++)
            #pragma unroll
            for (int q = 0; q < 4; q++)
                #pragma unroll
                for (int v = 0; v < 4; v++) acc[jj][i][q][v] = 0.f;

    float4 ra0, ra1;
    uint4  rb[NB];
    const int a_r  = tid >> 2;           // 0..127
    const int a_c8 = (tid & 3) * 8;      // 0,8,16,24
    const int b_r  = tid >> 2;           // 0..127
    const int b_g  = tid & 3;            // 16B granule

    auto gload = [&](int c) {
        const int kk = c << 5;
        const int gr = row0 + a_r;
        ra0 = make_float4(0.f, 0.f, 0.f, 0.f);
        ra1 = make_float4(0.f, 0.f, 0.f, 0.f);
        if (gr < M) {
            ra0 = *reinterpret_cast<const float4*>(&A[(size_t)gr * K + kk + a_c8]);
            ra1 = *reinterpret_cast<const float4*>(&A[(size_t)gr * K + kk + a_c8 + 4]);
        }
        #pragma unroll
        for (int jj = 0; jj < NB; jj++)
            rb[jj] = *reinterpret_cast<const uint4*>(
                &Bp[jj][(size_t)(col0 + b_r) * K + kk + b_g * 8]);
    };

    auto sstore = [&](int buf) {
        char* st = smem + buf * STAGE;
        __half2 h0 = __floats2half2_rn(ra0.x, ra0.y);
        __half2 h1 = __floats2half2_rn(ra0.z, ra0.w);
        __half2 h2 = __floats2half2_rn(ra1.x, ra1.y);
        __half2 h3 = __floats2half2_rn(ra1.z, ra1.w);
        uint4 hv;
        hv.x = *reinterpret_cast<uint32_t*>(&h0);
        hv.y = *reinterpret_cast<uint32_t*>(&h1);
        hv.z = *reinterpret_cast<uint32_t*>(&h2);
        hv.w = *reinterpret_cast<uint32_t*>(&h3);
        const uint32_t aoff = (uint32_t)(a_r * APAD + a_c8) * 2u;
        *reinterpret_cast<uint4*>(st + aoff) = hv;
        #pragma unroll
        for (int jj = 0; jj < NB; jj++) {
            const uint32_t boff = (uint32_t)(b_r * APAD + b_g * 8) * 2u;
            *reinterpret_cast<uint4*>(st + 10240 + jj * 10240 + boff) = rb[jj];
        }
    };

    const uint32_t smem_base = smem_u32(smem);

    auto compute = [&](int buf) {
        const uint32_t st = smem_base + buf * STAGE;
        #pragma unroll
        for (int j = 0; j < 2; j++) {
            uint32_t af[2][4];
            #pragma unroll
            for (int i = 0; i < 2; i++) {
                const uint32_t eoff = 2u * ((wm * 32 + i * 16 + (lane & 15)) * APAD +
                                            j * 16 + (lane >> 4) * 8);
                LDSM_X4(af[i][0], af[i][1], af[i][2], af[i][3], st + eoff);
            }
            #pragma unroll
            for (int jj = 0; jj < NB; jj++) {
                uint32_t bh[2][4];
                #pragma unroll
                for (int p = 0; p < 2; p++) {
                    const uint32_t eoff = 2u * ((wn * 32 + p * 16 + (lane & 15)) * APAD +
                                                j * 16 + (lane >> 4) * 8);
                    LDSM_X4(bh[p][0], bh[p][1], bh[p][2], bh[p][3],
                            st + 10240 + jj * 10240 + eoff);
                }
                #pragma unroll
                for (int i = 0; i < 2; i++)
                    #pragma unroll
                    for (int q = 0; q < 4; q++) {
                        const int p = q >> 1, s = q & 1;
                        MMA_F16(acc[jj][i][q],
                                af[i][0], af[i][1], af[i][2], af[i][3],
                                bh[p][s], bh[p][s + 2]);
                    }
            }
        }
    };

    gload(0);
    sstore(0);
    __syncthreads();

    for (int c = 0; c < NC; c++) {
        const int cur = c & 1;
        const bool has_next = (c + 1 < NC);
        if (has_next) gload(c + 1);
        compute(cur);
        if (has_next) {
            sstore(cur ^ 1);
            __syncthreads();
        }
    }

    #pragma unroll
    for (int i = 0; i < 2; i++) {
        const int r = row0 + wm * 32 + i * 16 + (lane >> 2);
        #pragma unroll
        for (int q = 0; q < 4; q++) {
            const int cc = col0 + wn * 32 + q * 8 + (lane & 3) * 2;
            if (r < M)
                *reinterpret_cast<__half2*>(&C0[(size_t)r * DO_DIM + cc]) =
                    __floats2half2_rn(acc[0][i][q][0], acc[0][i][q][1]);
            if (r + 8 < M)
                *reinterpret_cast<__half2*>(&C0[(size_t)(r + 8) * DO_DIM + cc]) =
                    __floats2half2_rn(acc[0][i][q][2], acc[0][i][q][3]);
            if (NB == 2) {
                if (r < M)
                    *reinterpret_cast<float2*>(&C1[(size_t)r * DO_DIM + cc]) =
                        make_float2(acc[1][i][q][0], acc[1][i][q][1]);
                if (r + 8 < M)
                    *reinterpret_cast<float2*>(&C1[(size_t)(r + 8) * DO_DIM + cc]) =
                        make_float2(acc[1][i][q][2], acc[1][i][q][3]);
            }
        }
    }
}

// ---------------------------------------------------------------------------
// Scatter body: one 512-thread block handles 512 edges.
// ---------------------------------------------------------------------------
__device__ __forceinline__
void scatter_body(const int* __restrict__ row, const int* __restrict__ col,
                  const float* __restrict__ ew, int e,
                  int* __restrict__ cursor, int2* __restrict__ edges, int blk)
{
    const int i = blk * 512 + threadIdx.x;
    if (i < e) {
        const int r = row[i];
        const int p = atomicAdd(&cursor[r], 1);
        edges[p] = make_int2(col[i], __float_as_int(ew[i]));
    }
}

// ---------------------------------------------------------------------------
// K1: W transpose+fp16 (y=0..2) + zero counts (y=3)
// ---------------------------------------------------------------------------
__global__ void prep_kernel(const float* __restrict__ W0,
                            const float* __restrict__ W1,
                            const float* __restrict__ Wr,
                            __half* __restrict__ o0,
                            __half* __restrict__ o1,
                            __half* __restrict__ oR,
                            int* __restrict__ c0, int* __restrict__ c1, int n)
{
    const int which = blockIdx.y;
    if (which == 3) {
        const int i = blockIdx.x * blockDim.x + threadIdx.x;
        if (i < n) { c0[i] = 0; c1[i] = 0; }
        return;
    }
    const float* W = (which == 0) ? W0 : (which == 1) ? W1 : Wr;
    __half* o      = (which == 0) ? o0 : (which == 1) ? o1 : oR;
    const int K    = (which == 0) ? 256 : 512;
    const int idx  = blockIdx.x * blockDim.x + threadIdx.x;
    if (idx >= 256 * K) return;
    const int nn = idx & 255;
    const int k  = idx >> 8;
    o[(size_t)nn * K + k] = __float2half_rn(W[(size_t)k * 256 + nn]);
}

// ---------------------------------------------------------------------------
// Hierarchical scan pieces
// ---------------------------------------------------------------------------
__device__ __forceinline__ int block_exscan256(int v, int tid, int* total)
{
    __shared__ int ws[8];
    const int lane = tid & 31, wid = tid >> 5;
    int x = v;
    #pragma unroll
    for (int d = 1; d < 32; d <<= 1) {
        int y = __shfl_up_sync(0xffffffffu, x, d);
        if (lane >= d) x += y;
    }
    if (lane == 31) ws[wid] = x;
    __syncthreads();
    if (wid == 0 && lane < 8) {
        int y = ws[lane];
        #pragma unroll
        for (int d = 1; d < 8; d <<= 1) {
            int z = __shfl_up_sync(0xffu, y, d);
            if (lane >= d) y += z;
        }
        ws[lane] = y;
    }
    __syncthreads();
    const int warp_off = (wid > 0) ? ws[wid - 1] : 0;
    *total = ws[7];
    return warp_off + x - v;
}

__global__ void block_sums_kernel(const int* __restrict__ cA, const int* __restrict__ cB,
                                  int n, int* __restrict__ bsums)
{
    const int* cnt = blockIdx.y ? cB : cA;
    const int idx = blockIdx.x * 256 + threadIdx.x;
    int v = (idx < n) ? cnt[idx] : 0;
    int total;
    block_exscan256(v, threadIdx.x, &total);
    if (threadIdx.x == 0) bsums[blockIdx.y * 256 + blockIdx.x] = total;
}

__global__ void scan_tops_kernel(int* __restrict__ bsums, int nb)
{
    int* b = bsums + blockIdx.x * 256;
    const int tid = threadIdx.x;
    int v = (tid < nb) ? b[tid] : 0;
    int total;
    const int e = block_exscan256(v, tid, &total);
    if (tid < nb) b[tid] = e;
}

__global__ void scan_final_kernel(const int* __restrict__ cA, const int* __restrict__ cB,
                                  int n, const int* __restrict__ bsums,
                                  int* __restrict__ oA, int* __restrict__ uA,
                                  int* __restrict__ oB, int* __restrict__ uB)
{
    const int* cnt = blockIdx.y ? cB : cA;
    int* offs      = blockIdx.y ? oB : oA;
    int* cursor    = blockIdx.y ? uB : uA;
    const int idx  = blockIdx.x * 256 + threadIdx.x;
    int v = (idx < n) ? cnt[idx] : 0;
    int total;
    const int e = block_exscan256(v, threadIdx.x, &total) +
                  bsums[blockIdx.y * 256 + blockIdx.x];
    if (idx < n) { offs[idx] = e; cursor[idx] = e; }
}

// ---------------------------------------------------------------------------
// K2: gemm1 (graph 1, dual output) + histogram (both graphs) — fat kernel.
// GEMM blocks first so they start immediately; hist blocks (short,
// atomic-bound, like scatter) fill in behind.
// ---------------------------------------------------------------------------
__global__ __launch_bounds__(512)
void mega2_kernel(const float* __restrict__ x1,
                  const __half* __restrict__ w1, const __half* __restrict__ wr,
                  __half* __restrict__ hproj1, float* __restrict__ res1, int N1,
                  const int* __restrict__ row0, int* __restrict__ cnt0,
                  const int* __restrict__ row1, int* __restrict__ cnt1,
                  int E, int gemm_blocks)
{
    extern __shared__ char smem[];
    const int b = blockIdx.x;
    if (b < gemm_blocks) {
        gemm_body512<2>(x1, w1, wr, hproj1, res1, N1, 512,
                        b & 1, b >> 1, smem);
        return;
    }
    const int sb  = b - gemm_blocks;
    const int per = (E + 511) / 512;
    if (sb < per) {
        const int i = sb * 512 + threadIdx.x;
        if (i < E) atomicAdd(&cnt0[row0[i]], 1);
    } else {
        const int i = (sb - per) * 512 + threadIdx.x;
        if (i < E) atomicAdd(&cnt1[row1[i]], 1);
    }
}

// ---------------------------------------------------------------------------
// K4: gemm0 (graph 0) + scatter (both graphs)
// ---------------------------------------------------------------------------
__global__ __launch_bounds__(512)
void mega1_kernel(const float* __restrict__ x0,
                  const __half* __restrict__ w0,
                  __half* __restrict__ hproj0, int N0,
                  const int* __restrict__ row0, const int* __restrict__ col0,
                  const float* __restrict__ ew0, int* __restrict__ cur0,
                  int2* __restrict__ edge0,
                  const int* __restrict__ row1, const int* __restrict__ col1,
                  const float* __restrict__ ew1, int* __restrict__ cur1,
                  int2* __restrict__ edge1, int E, int gemm_blocks)
{
    extern __shared__ char smem[];
    const int b = blockIdx.x;
    if (b < gemm_blocks) {
        gemm_body512<1>(x0, w0, nullptr, hproj0, nullptr, N0, 256,
                        b & 1, b >> 1, smem);
        return;
    }
    const int sb = b - gemm_blocks;
    const int per = (E + 511) / 512;
    if (sb < per)
        scatter_body(row0, col0, ew0, E, cur0, edge0, sb);
    else
        scatter_body(row1, col1, ew1, E, cur1, edge1, sb - per);
}

// ---------------------------------------------------------------------------
// K5: aggregate + LayerNorm, both graphs (blockIdx.y), 256 threads, 8 rows/blk
// ---------------------------------------------------------------------------
__global__ __launch_bounds__(256)
void aggregate_ln_kernel(const __half* __restrict__ hpA, const float* __restrict__ rsA,
                         const int* __restrict__ offA, const int* __restrict__ cntA,
                         const int2* __restrict__ edgA,
                         const float* __restrict__ gA, const float* __restrict__ bA,
                         const __half* __restrict__ hpB, const float* __restrict__ rsB,
                         const int* __restrict__ offB, const int* __restrict__ cntB,
                         const int2* __restrict__ edgB,
                         const float* __restrict__ gB, const float* __restrict__ bB,
                         float* __restrict__ out, int nrows)
{
    const int which = blockIdx.y;
    const __half* hproj = which ? hpB : hpA;
    const float* resid  = which ? rsB : rsA;
    const int* offs     = which ? offB : offA;
    const int* cnt      = which ? cntB : cntA;
    const int2* edges   = which ? edgB : edgA;
    const float* gamma  = which ? gB : gA;
    const float* beta   = which ? bB : bA;
    float* o            = out + (size_t)which * nrows * DO_DIM;

    const int warp_id = blockIdx.x * 8 + (threadIdx.x >> 5);
    if (warp_id >= nrows) return;
    const int lane   = threadIdx.x & 31;
    const int base_c = lane * 8;

    const int start = offs[warp_id];
    const int n     = cnt[warp_id];
    const int2* ep  = edges + start;

    const float4* rp = reinterpret_cast<const float4*>(
        resid + (size_t)warp_id * DO_DIM + base_c);
    float4 a0 = rp[0];
    float4 a1 = rp[1];

    int e = 0;
    for (; e + 4 <= n; e += 4) {
        const int2 e0 = ep[e], e1 = ep[e + 1], e2 = ep[e + 2], e3 = ep[e + 3];
        const uint4 h0 = *(reinterpret_cast<const uint4*>(hproj + (size_t)e0.x * DO_DIM) + lane);
        const uint4 h1 = *(reinterpret_cast<const uint4*>(hproj + (size_t)e1.x * DO_DIM) + lane);
        const uint4 h2 = *(reinterpret_cast<const uint4*>(hproj + (size_t)e2.x * DO_DIM) + lane);
        const uint4 h3 = *(reinterpret_cast<const uint4*>(hproj + (size_t)e3.x * DO_DIM) + lane);
        const uint4  hvv[4] = {h0, h1, h2, h3};
        const float  ww[4]  = {__int_as_float(e0.y), __int_as_float(e1.y),
                               __int_as_float(e2.y), __int_as_float(e3.y)};
        #pragma unroll
        for (int u = 0; u < 4; u++) {
            const __half2* hh = reinterpret_cast<const __half2*>(&hvv[u]);
            const float w = ww[u];
            float2 f;
            f = __half22float2(hh[0]); a0.x += w * f.x; a0.y += w * f.y;
            f = __half22float2(hh[1]); a0.z += w * f.x; a0.w += w * f.y;
            f = __half22float2(hh[2]); a1.x += w * f.x; a1.y += w * f.y;
            f = __half22float2(hh[3]); a1.z += w * f.x; a1.w += w * f.y;
        }
    }
    for (; e < n; e++) {
        const int2 ed = ep[e];
        const float w = __int_as_float(ed.y);
        const uint4 hv = *(reinterpret_cast<const uint4*>(
            hproj + (size_t)ed.x * DO_DIM) + lane);
        const __half2* hh = reinterpret_cast<const __half2*>(&hv);
        float2 f;
        f = __half22float2(hh[0]); a0.x += w * f.x; a0.y += w * f.y;
        f = __half22float2(hh[1]); a0.z += w * f.x; a0.w += w * f.y;
        f = __half22float2(hh[2]); a1.x += w * f.x; a1.y += w * f.y;
        f = __half22float2(hh[3]); a1.z += w * f.x; a1.w += w * f.y;
    }

    float s  = a0.x + a0.y + a0.z + a0.w + a1.x + a1.y + a1.z + a1.w;
    float s2 = a0.x*a0.x + a0.y*a0.y + a0.z*a0.z + a0.w*a0.w
             + a1.x*a1.x + a1.y*a1.y + a1.z*a1.z + a1.w*a1.w;
    #pragma unroll
    for (int d = 16; d > 0; d >>= 1) {
        s  += __shfl_xor_sync(0xffffffffu, s,  d);
        s2 += __shfl_xor_sync(0xffffffffu, s2, d);
    }
    const float mu  = s * (1.f / DO_DIM);
    const float var = s2 * (1.f / DO_DIM) - mu * mu;
    const float inv = rsqrtf(var + LN_EPS);

    const float4 gv0 = *reinterpret_cast<const float4*>(&gamma[base_c]);
    const float4 gv1 = *reinterpret_cast<const float4*>(&gamma[base_c + 4]);
    const float4 bv0 = *reinterpret_cast<const float4*>(&beta [base_c]);
    const float4 bv1 = *reinterpret_cast<const float4*>(&beta [base_c + 4]);

    float4 o0, o1;
    o0.x = (a0.x - mu) * inv * gv0.x + bv0.x;
    o0.y = (a0.y - mu) * inv * gv0.y + bv0.y;
    o0.z = (a0.z - mu) * inv * gv0.z + bv0.z;
    o0.w = (a0.w - mu) * inv * gv0.w + bv0.w;
    o1.x = (a1.x - mu) * inv * gv1.x + bv1.x;
    o1.y = (a1.y - mu) * inv * gv1.y + bv1.y;
    o1.z = (a1.z - mu) * inv * gv1.z + bv1.z;
    o1.w = (a1.w - mu) * inv * gv1.w + bv1.w;

    float* op = o + (size_t)warp_id * DO_DIM + base_c;
    *reinterpret_cast<float4*>(op)     = o0;
    *reinterpret_cast<float4*>(op + 4) = o1;
}

// ---------------------------------------------------------------------------
// Launch
// ---------------------------------------------------------------------------
extern "C" void kernel_launch(void* const* d_in, const int* in_sizes, int n_in,
                              void* d_out, int out_size)
{
    const float* x0    = (const float*)d_in[0];
    const float* x1    = (const float*)d_in[1];
    const float* W0    = (const float*)d_in[2];
    const float* W1    = (const float*)d_in[3];
    const float* Wres1 = (const float*)d_in[4];
    const float* g0    = (const float*)d_in[5];
    const float* b0    = (const float*)d_in[6];
    const float* g1    = (const float*)d_in[7];
    const float* b1    = (const float*)d_in[8];
    const float* ew0   = (const float*)d_in[9];
    const float* ew1   = (const float*)d_in[10];
    const int*   row0  = (const int*)d_in[11];
    const int*   col0  = (const int*)d_in[12];
    const int*   row1  = (const int*)d_in[13];
    const int*   col1  = (const int*)d_in[14];
    float* out = (float*)d_out;

    const int D0 = 256, D1 = 512;
    const int N0 = in_sizes[0] / D0;
    const int N1 = in_sizes[1] / D1;
    const int E  = in_sizes[9];

    __half *hproj0, *hproj1, *w0, *w1, *wr;
    float *res1;
    int *cnt0, *cnt1, *off0, *off1, *cur0, *cur1, *bsum;
    int2 *edge0, *edge1;
    cudaGetSymbolAddress((void**)&hproj0, g_hproj0);
    cudaGetSymbolAddress((void**)&hproj1, g_hproj1);
    cudaGetSymbolAddress((void**)&res1,   g_res1);
    cudaGetSymbolAddress((void**)&cnt0,   g_cnt0);
    cudaGetSymbolAddress((void**)&cnt1,   g_cnt1);
    cudaGetSymbolAddress((void**)&off0,   g_off0);
    cudaGetSymbolAddress((void**)&off1,   g_off1);
    cudaGetSymbolAddress((void**)&cur0,   g_cur0);
    cudaGetSymbolAddress((void**)&cur1,   g_cur1);
    cudaGetSymbolAddress((void**)&bsum,   g_bsum);
    cudaGetSymbolAddress((void**)&edge0,  g_edge0);
    cudaGetSymbolAddress((void**)&edge1,  g_edge1);
    cudaGetSymbolAddress((void**)&w0,     g_w0);
    cudaGetSymbolAddress((void**)&w1,     g_w1);
    cudaGetSymbolAddress((void**)&wr,     g_wr);

    // K1: W prep + zero counts
    {
        dim3 g((256 * 512 + 255) / 256, 4);
        prep_kernel<<<g, 256>>>(W0, W1, Wres1, w0, w1, wr, cnt0, cnt1,
                                (N0 > N1 ? N0 : N1));
    }
    // K2: gemm1 + histogram (fat)
    {
        constexpr int SMEM2 = 2 * (10240 * 3);          // 61440
        cudaFuncSetAttribute(mega2_kernel,
                             cudaFuncAttributeMaxDynamicSharedMemorySize, SMEM2);
        const int gemm_blocks = 2 * ((N1 + 127) / 128);
        const int per = (E + 511) / 512;
        mega2_kernel<<<gemm_blocks + 2 * per, 512, SMEM2>>>(
            x1, w1, wr, hproj1, res1, N1,
            row0, cnt0, row1, cnt1, E, gemm_blocks);
    }
    // K3: scan
    {
        const int nblk = (N0 + 255) / 256;
        dim3 g(nblk, 2);
        block_sums_kernel<<<g, 256>>>(cnt0, cnt1, N0, bsum);
        scan_tops_kernel<<<2, 256>>>(bsum, nblk);
        scan_final_kernel<<<g, 256>>>(cnt0, cnt1, N0, bsum,
                                      off0, cur0, off1, cur1);
    }
    // K4: gemm0 + scatter both
    {
        constexpr int SMEM1 = 2 * (10240 * 2);          // 40960
        cudaFuncSetAttribute(mega1_kernel,
                             cudaFuncAttributeMaxDynamicSharedMemorySize, SMEM1);
        const int gemm_blocks = 2 * ((N0 + 127) / 128);
        const int per = (E + 511) / 512;
        mega1_kernel<<<gemm_blocks + 2 * per, 512, SMEM1>>>(
            x0, w0, hproj0, N0,
            row0, col0, ew0, cur0, edge0,
            row1, col1, ew1, cur1, edge1, E, gemm_blocks);
    }
    // K5: aggregate + layernorm (both graphs)
    {
        dim3 g((N0 + 7) / 8, 2);
        aggregate_ln_kernel<<<g, 256>>>(hproj0, x0,   off0, cnt0, edge0, g0, b0,
                                        hproj1, res1, off1, cnt1, edge1, g1, b1,
                                        out, N0);
    }
}

// round 16
// speedup vs baseline: 1.4386x; 1.4386x over previous
#include <cuda_runtime.h>
#include <cuda_fp16.h>
#include <cstdint>

// ---------------------------------------------------------------------------
// Shapes: N0 = N1 = 50000, D0 = 256, D1 = 512, DO = 256, E = 1600000
// ---------------------------------------------------------------------------
#define MAX_N   50000
#define MAX_E   1600000
#define DO_DIM  256
#define LN_EPS  1e-5f

// ---------------------------------------------------------------------------
// Device scratch (static — no allocations allowed)
// ---------------------------------------------------------------------------
__device__ __align__(16) __half g_hproj0[MAX_N * DO_DIM];
__device__ __align__(16) __half g_hproj1[MAX_N * DO_DIM];
__device__ __align__(16) float  g_res1  [MAX_N * DO_DIM];

__device__ int   g_cnt0[MAX_N],  g_cnt1[MAX_N];
__device__ int   g_off0[MAX_N],  g_off1[MAX_N];
__device__ int   g_cur0[MAX_N],  g_cur1[MAX_N];
__device__ int   g_bsum[2 * 256];
__device__ int2  g_edge0[MAX_E], g_edge1[MAX_E];

// W transposed fp16: [N=256][K] row-major
__device__ __align__(16) __half g_w0[256 * 256];
__device__ __align__(16) __half g_w1[256 * 512];
__device__ __align__(16) __half g_wr[256 * 512];

// ---------------------------------------------------------------------------
// PTX helpers (compute_103-safe)
// ---------------------------------------------------------------------------
__device__ __forceinline__ uint32_t smem_u32(const void* p) {
    uint32_t a;
    asm("{ .reg .u64 t; cvta.to.shared.u64 t, %1; cvt.u32.u64 %0, t; }"
        : "=r"(a) : "l"(p));
    return a;
}

#define LDSM_X4(r0, r1, r2, r3, addr)                                        \
    asm volatile("ldmatrix.sync.aligned.m8n8.x4.shared.b16 {%0,%1,%2,%3}, [%4];" \
        : "=r"(r0), "=r"(r1), "=r"(r2), "=r"(r3) : "r"(addr))

#define MMA_F16(d, a0, a1, a2, a3, b0, b1)                                   \
    asm volatile("mma.sync.aligned.m16n8k16.row.col.f32.f16.f16.f32 "        \
        "{%0,%1,%2,%3},{%4,%5,%6,%7},{%8,%9},{%0,%1,%2,%3};"                 \
        : "+f"((d)[0]), "+f"((d)[1]), "+f"((d)[2]), "+f"((d)[3])             \
        : "r"(a0), "r"(a1), "r"(a2), "r"(a3), "r"(b0), "r"(b1))

// ---------------------------------------------------------------------------
// 512-thread GEMM body. Block tile 128(M) x 128(N), K-chunk 32,
// double-buffered smem, 16 warps @ 32x32 warp tiles.
//   C0 (fp16) = A @ B0^T ; [NB==2] C1 (fp32) = A @ B1^T
// Stage bytes: A [0,10240) ; B[jj] at 10240 + jj*10240
// ---------------------------------------------------------------------------
template <int NB>
__device__ __forceinline__
void gemm_body512(const float* __restrict__ A,
                  const __half* __restrict__ B0,
                  const __half* __restrict__ B1,
                  __half* __restrict__ C0, float* __restrict__ C1,
                  int M, int K, int bx, int by, char* smem)
{
    constexpr int APAD  = 40;
    constexpr int STAGE = 10240 * (1 + NB);

    const int tid  = threadIdx.x;
    const int lane = tid & 31;
    const int wid  = tid >> 5;           // 0..15
    const int wm   = wid >> 2;           // 0..3 (M)
    const int wn   = wid & 3;            // 0..3 (N)
    const int row0 = by * 128;
    const int col0 = bx * 128;

    const int NC = K >> 5;
    const __half* Bp[2] = {B0, B1};

    float acc[NB][2][4][4];
    #pragma unroll
    for (int jj = 0; jj < NB; jj++)
        #pragma unroll
        for (int i = 0; i < 2; i++)
            #pragma unroll
            for (int q = 0; q < 4; q++)
                #pragma unroll
                for (int v = 0; v < 4; v++) acc[jj][i][q][v] = 0.f;

    float4 ra0, ra1;
    uint4  rb[NB];
    const int a_r  = tid >> 2;           // 0..127
    const int a_c8 = (tid & 3) * 8;      // 0,8,16,24
    const int b_r  = tid >> 2;           // 0..127
    const int b_g  = tid & 3;            // 16B granule

    auto gload = [&](int c) {
        const int kk = c << 5;
        const int gr = row0 + a_r;
        ra0 = make_float4(0.f, 0.f, 0.f, 0.f);
        ra1 = make_float4(0.f, 0.f, 0.f, 0.f);
        if (gr < M) {
            ra0 = *reinterpret_cast<const float4*>(&A[(size_t)gr * K + kk + a_c8]);
            ra1 = *reinterpret_cast<const float4*>(&A[(size_t)gr * K + kk + a_c8 + 4]);
        }
        #pragma unroll
        for (int jj = 0; jj < NB; jj++)
            rb[jj] = *reinterpret_cast<const uint4*>(
                &Bp[jj][(size_t)(col0 + b_r) * K + kk + b_g * 8]);
    };

    auto sstore = [&](int buf) {
        char* st = smem + buf * STAGE;
        __half2 h0 = __floats2half2_rn(ra0.x, ra0.y);
        __half2 h1 = __floats2half2_rn(ra0.z, ra0.w);
        __half2 h2 = __floats2half2_rn(ra1.x, ra1.y);
        __half2 h3 = __floats2half2_rn(ra1.z, ra1.w);
        uint4 hv;
        hv.x = *reinterpret_cast<uint32_t*>(&h0);
        hv.y = *reinterpret_cast<uint32_t*>(&h1);
        hv.z = *reinterpret_cast<uint32_t*>(&h2);
        hv.w = *reinterpret_cast<uint32_t*>(&h3);
        const uint32_t aoff = (uint32_t)(a_r * APAD + a_c8) * 2u;
        *reinterpret_cast<uint4*>(st + aoff) = hv;
        #pragma unroll
        for (int jj = 0; jj < NB; jj++) {
            const uint32_t boff = (uint32_t)(b_r * APAD + b_g * 8) * 2u;
            *reinterpret_cast<uint4*>(st + 10240 + jj * 10240 + boff) = rb[jj];
        }
    };

    const uint32_t smem_base = smem_u32(smem);

    auto compute = [&](int buf) {
        const uint32_t st = smem_base + buf * STAGE;
        #pragma unroll
        for (int j = 0; j < 2; j++) {
            uint32_t af[2][4];
            #pragma unroll
            for (int i = 0; i < 2; i++) {
                const uint32_t eoff = 2u * ((wm * 32 + i * 16 + (lane & 15)) * APAD +
                                            j * 16 + (lane >> 4) * 8);
                LDSM_X4(af[i][0], af[i][1], af[i][2], af[i][3], st + eoff);
            }
            #pragma unroll
            for (int jj = 0; jj < NB; jj++) {
                uint32_t bh[2][4];
                #pragma unroll
                for (int p = 0; p < 2; p++) {
                    const uint32_t eoff = 2u * ((wn * 32 + p * 16 + (lane & 15)) * APAD +
                                                j * 16 + (lane >> 4) * 8);
                    LDSM_X4(bh[p][0], bh[p][1], bh[p][2], bh[p][3],
                            st + 10240 + jj * 10240 + eoff);
                }
                #pragma unroll
                for (int i = 0; i < 2; i++)
                    #pragma unroll
                    for (int q = 0; q < 4; q++) {
                        const int p = q >> 1, s = q & 1;
                        MMA_F16(acc[jj][i][q],
                                af[i][0], af[i][1], af[i][2], af[i][3],
                                bh[p][s], bh[p][s + 2]);
                    }
            }
        }
    };

    gload(0);
    sstore(0);
    __syncthreads();

    for (int c = 0; c < NC; c++) {
        const int cur = c & 1;
        const bool has_next = (c + 1 < NC);
        if (has_next) gload(c + 1);
        compute(cur);
        if (has_next) {
            sstore(cur ^ 1);
            __syncthreads();
        }
    }

    #pragma unroll
    for (int i = 0; i < 2; i++) {
        const int r = row0 + wm * 32 + i * 16 + (lane >> 2);
        #pragma unroll
        for (int q = 0; q < 4; q++) {
            const int cc = col0 + wn * 32 + q * 8 + (lane & 3) * 2;
            if (r < M)
                *reinterpret_cast<__half2*>(&C0[(size_t)r * DO_DIM + cc]) =
                    __floats2half2_rn(acc[0][i][q][0], acc[0][i][q][1]);
            if (r + 8 < M)
                *reinterpret_cast<__half2*>(&C0[(size_t)(r + 8) * DO_DIM + cc]) =
                    __floats2half2_rn(acc[0][i][q][2], acc[0][i][q][3]);
            if (NB == 2) {
                if (r < M)
                    *reinterpret_cast<float2*>(&C1[(size_t)r * DO_DIM + cc]) =
                        make_float2(acc[1][i][q][0], acc[1][i][q][1]);
                if (r + 8 < M)
                    *reinterpret_cast<float2*>(&C1[(size_t)(r + 8) * DO_DIM + cc]) =
                        make_float2(acc[1][i][q][2], acc[1][i][q][3]);
            }
        }
    }
}

// ---------------------------------------------------------------------------
// Scatter body: one 512-thread block handles 512 edges.
// ---------------------------------------------------------------------------
__device__ __forceinline__
void scatter_body(const int* __restrict__ row, const int* __restrict__ col,
                  const float* __restrict__ ew, int e,
                  int* __restrict__ cursor, int2* __restrict__ edges, int blk)
{
    const int i = blk * 512 + threadIdx.x;
    if (i < e) {
        const int r = row[i];
        const int p = atomicAdd(&cursor[r], 1);
        edges[p] = make_int2(col[i], __float_as_int(ew[i]));
    }
}

// ---------------------------------------------------------------------------
// K1: W transpose+fp16 (y=0..2) + zero counts (y=3)
// ---------------------------------------------------------------------------
__global__ void prep_kernel(const float* __restrict__ W0,
                            const float* __restrict__ W1,
                            const float* __restrict__ Wr,
                            __half* __restrict__ o0,
                            __half* __restrict__ o1,
                            __half* __restrict__ oR,
                            int* __restrict__ c0, int* __restrict__ c1, int n)
{
    const int which = blockIdx.y;
    if (which == 3) {
        const int i = blockIdx.x * blockDim.x + threadIdx.x;
        if (i < n) { c0[i] = 0; c1[i] = 0; }
        return;
    }
    const float* W = (which == 0) ? W0 : (which == 1) ? W1 : Wr;
    __half* o      = (which == 0) ? o0 : (which == 1) ? o1 : oR;
    const int K    = (which == 0) ? 256 : 512;
    const int idx  = blockIdx.x * blockDim.x + threadIdx.x;
    if (idx >= 256 * K) return;
    const int nn = idx & 255;
    const int k  = idx >> 8;
    o[(size_t)nn * K + k] = __float2half_rn(W[(size_t)k * 256 + nn]);
}

// ---------------------------------------------------------------------------
// K2: histogram (both graphs)
// ---------------------------------------------------------------------------
__global__ void hist2_kernel(const int* __restrict__ rowA, int* __restrict__ cntA,
                             const int* __restrict__ rowB, int* __restrict__ cntB,
                             int e)
{
    const int* row = blockIdx.y ? rowB : rowA;
    int* cnt       = blockIdx.y ? cntB : cntA;
    int i = blockIdx.x * blockDim.x + threadIdx.x;
    if (i < e) atomicAdd(&cnt[row[i]], 1);
}

// ---------------------------------------------------------------------------
// Hierarchical scan pieces
// ---------------------------------------------------------------------------
__device__ __forceinline__ int block_exscan256(int v, int tid, int* total)
{
    __shared__ int ws[8];
    const int lane = tid & 31, wid = tid >> 5;
    int x = v;
    #pragma unroll
    for (int d = 1; d < 32; d <<= 1) {
        int y = __shfl_up_sync(0xffffffffu, x, d);
        if (lane >= d) x += y;
    }
    if (lane == 31) ws[wid] = x;
    __syncthreads();
    if (wid == 0 && lane < 8) {
        int y = ws[lane];
        #pragma unroll
        for (int d = 1; d < 8; d <<= 1) {
            int z = __shfl_up_sync(0xffu, y, d);
            if (lane >= d) y += z;
        }
        ws[lane] = y;
    }
    __syncthreads();
    const int warp_off = (wid > 0) ? ws[wid - 1] : 0;
    *total = ws[7];
    return warp_off + x - v;
}

__global__ void block_sums_kernel(const int* __restrict__ cA, const int* __restrict__ cB,
                                  int n, int* __restrict__ bsums)
{
    const int* cnt = blockIdx.y ? cB : cA;
    const int idx = blockIdx.x * 256 + threadIdx.x;
    int v = (idx < n) ? cnt[idx] : 0;
    int total;
    block_exscan256(v, threadIdx.x, &total);
    if (threadIdx.x == 0) bsums[blockIdx.y * 256 + blockIdx.x] = total;
}

__global__ void scan_tops_kernel(int* __restrict__ bsums, int nb)
{
    int* b = bsums + blockIdx.x * 256;
    const int tid = threadIdx.x;
    int v = (tid < nb) ? b[tid] : 0;
    int total;
    const int e = block_exscan256(v, tid, &total);
    if (tid < nb) b[tid] = e;
}

__global__ void scan_final_kernel(const int* __restrict__ cA, const int* __restrict__ cB,
                                  int n, const int* __restrict__ bsums,
                                  int* __restrict__ oA, int* __restrict__ uA,
                                  int* __restrict__ oB, int* __restrict__ uB)
{
    const int* cnt = blockIdx.y ? cB : cA;
    int* offs      = blockIdx.y ? oB : oA;
    int* cursor    = blockIdx.y ? uB : uA;
    const int idx  = blockIdx.x * 256 + threadIdx.x;
    int v = (idx < n) ? cnt[idx] : 0;
    int total;
    const int e = block_exscan256(v, threadIdx.x, &total) +
                  bsums[blockIdx.y * 256 + blockIdx.x];
    if (idx < n) { offs[idx] = e; cursor[idx] = e; }
}

// ---------------------------------------------------------------------------
// K4: gemm1 (graph 1, dual output, 512 threads)
// ---------------------------------------------------------------------------
__global__ __launch_bounds__(512)
void gemm2_kernel(const float* __restrict__ x1,
                  const __half* __restrict__ w1, const __half* __restrict__ wr,
                  __half* __restrict__ hproj1, float* __restrict__ res1, int N1)
{
    extern __shared__ char smem[];
    gemm_body512<2>(x1, w1, wr, hproj1, res1, N1, 512,
                    blockIdx.x, blockIdx.y, smem);
}

// ---------------------------------------------------------------------------
// K5: gemm0 (graph 0) + scatter (both graphs)
// ---------------------------------------------------------------------------
__global__ __launch_bounds__(512)
void mega1_kernel(const float* __restrict__ x0,
                  const __half* __restrict__ w0,
                  __half* __restrict__ hproj0, int N0,
                  const int* __restrict__ row0, const int* __restrict__ col0,
                  const float* __restrict__ ew0, int* __restrict__ cur0,
                  int2* __restrict__ edge0,
                  const int* __restrict__ row1, const int* __restrict__ col1,
                  const float* __restrict__ ew1, int* __restrict__ cur1,
                  int2* __restrict__ edge1, int E, int gemm_blocks)
{
    extern __shared__ char smem[];
    const int b = blockIdx.x;
    if (b < gemm_blocks) {
        gemm_body512<1>(x0, w0, nullptr, hproj0, nullptr, N0, 256,
                        b & 1, b >> 1, smem);
        return;
    }
    const int sb = b - gemm_blocks;
    const int per = (E + 511) / 512;
    if (sb < per)
        scatter_body(row0, col0, ew0, E, cur0, edge0, sb);
    else
        scatter_body(row1, col1, ew1, E, cur1, edge1, sb - per);
}

// ---------------------------------------------------------------------------
// K6: aggregate + LayerNorm, both graphs (blockIdx.y), 256 threads, 8 rows/blk
// ---------------------------------------------------------------------------
__global__ __launch_bounds__(256)
void aggregate_ln_kernel(const __half* __restrict__ hpA, const float* __restrict__ rsA,
                         const int* __restrict__ offA, const int* __restrict__ cntA,
                         const int2* __restrict__ edgA,
                         const float* __restrict__ gA, const float* __restrict__ bA,
                         const __half* __restrict__ hpB, const float* __restrict__ rsB,
                         const int* __restrict__ offB, const int* __restrict__ cntB,
                         const int2* __restrict__ edgB,
                         const float* __restrict__ gB, const float* __restrict__ bB,
                         float* __restrict__ out, int nrows)
{
    const int which = blockIdx.y;
    const __half* hproj = which ? hpB : hpA;
    const float* resid  = which ? rsB : rsA;
    const int* offs     = which ? offB : offA;
    const int* cnt      = which ? cntB : cntA;
    const int2* edges   = which ? edgB : edgA;
    const float* gamma  = which ? gB : gA;
    const float* beta   = which ? bB : bA;
    float* o            = out + (size_t)which * nrows * DO_DIM;

    const int warp_id = blockIdx.x * 8 + (threadIdx.x >> 5);
    if (warp_id >= nrows) return;
    const int lane   = threadIdx.x & 31;
    const int base_c = lane * 8;

    const int start = offs[warp_id];
    const int n     = cnt[warp_id];
    const int2* ep  = edges + start;

    const float4* rp = reinterpret_cast<const float4*>(
        resid + (size_t)warp_id * DO_DIM + base_c);
    float4 a0 = rp[0];
    float4 a1 = rp[1];

    int e = 0;
    for (; e + 4 <= n; e += 4) {
        const int2 e0 = ep[e], e1 = ep[e + 1], e2 = ep[e + 2], e3 = ep[e + 3];
        const uint4 h0 = *(reinterpret_cast<const uint4*>(hproj + (size_t)e0.x * DO_DIM) + lane);
        const uint4 h1 = *(reinterpret_cast<const uint4*>(hproj + (size_t)e1.x * DO_DIM) + lane);
        const uint4 h2 = *(reinterpret_cast<const uint4*>(hproj + (size_t)e2.x * DO_DIM) + lane);
        const uint4 h3 = *(reinterpret_cast<const uint4*>(hproj + (size_t)e3.x * DO_DIM) + lane);
        const uint4  hvv[4] = {h0, h1, h2, h3};
        const float  ww[4]  = {__int_as_float(e0.y), __int_as_float(e1.y),
                               __int_as_float(e2.y), __int_as_float(e3.y)};
        #pragma unroll
        for (int u = 0; u < 4; u++) {
            const __half2* hh = reinterpret_cast<const __half2*>(&hvv[u]);
            const float w = ww[u];
            float2 f;
            f = __half22float2(hh[0]); a0.x += w * f.x; a0.y += w * f.y;
            f = __half22float2(hh[1]); a0.z += w * f.x; a0.w += w * f.y;
            f = __half22float2(hh[2]); a1.x += w * f.x; a1.y += w * f.y;
            f = __half22float2(hh[3]); a1.z += w * f.x; a1.w += w * f.y;
        }
    }
    for (; e < n; e++) {
        const int2 ed = ep[e];
        const float w = __int_as_float(ed.y);
        const uint4 hv = *(reinterpret_cast<const uint4*>(
            hproj + (size_t)ed.x * DO_DIM) + lane);
        const __half2* hh = reinterpret_cast<const __half2*>(&hv);
        float2 f;
        f = __half22float2(hh[0]); a0.x += w * f.x; a0.y += w * f.y;
        f = __half22float2(hh[1]); a0.z += w * f.x; a0.w += w * f.y;
        f = __half22float2(hh[2]); a1.x += w * f.x; a1.y += w * f.y;
        f = __half22float2(hh[3]); a1.z += w * f.x; a1.w += w * f.y;
    }

    float s  = a0.x + a0.y + a0.z + a0.w + a1.x + a1.y + a1.z + a1.w;
    float s2 = a0.x*a0.x + a0.y*a0.y + a0.z*a0.z + a0.w*a0.w
             + a1.x*a1.x + a1.y*a1.y + a1.z*a1.z + a1.w*a1.w;
    #pragma unroll
    for (int d = 16; d > 0; d >>= 1) {
        s  += __shfl_xor_sync(0xffffffffu, s,  d);
        s2 += __shfl_xor_sync(0xffffffffu, s2, d);
    }
    const float mu  = s * (1.f / DO_DIM);
    const float var = s2 * (1.f / DO_DIM) - mu * mu;
    const float inv = rsqrtf(var + LN_EPS);

    const float4 gv0 = *reinterpret_cast<const float4*>(&gamma[base_c]);
    const float4 gv1 = *reinterpret_cast<const float4*>(&gamma[base_c + 4]);
    const float4 bv0 = *reinterpret_cast<const float4*>(&beta [base_c]);
    const float4 bv1 = *reinterpret_cast<const float4*>(&beta [base_c + 4]);

    float4 o0, o1;
    o0.x = (a0.x - mu) * inv * gv0.x + bv0.x;
    o0.y = (a0.y - mu) * inv * gv0.y + bv0.y;
    o0.z = (a0.z - mu) * inv * gv0.z + bv0.z;
    o0.w = (a0.w - mu) * inv * gv0.w + bv0.w;
    o1.x = (a1.x - mu) * inv * gv1.x + bv1.x;
    o1.y = (a1.y - mu) * inv * gv1.y + bv1.y;
    o1.z = (a1.z - mu) * inv * gv1.z + bv1.z;
    o1.w = (a1.w - mu) * inv * gv1.w + bv1.w;

    float* op = o + (size_t)warp_id * DO_DIM + base_c;
    *reinterpret_cast<float4*>(op)     = o0;
    *reinterpret_cast<float4*>(op + 4) = o1;
}

// ---------------------------------------------------------------------------
// Launch
// ---------------------------------------------------------------------------
extern "C" void kernel_launch(void* const* d_in, const int* in_sizes, int n_in,
                              void* d_out, int out_size)
{
    const float* x0    = (const float*)d_in[0];
    const float* x1    = (const float*)d_in[1];
    const float* W0    = (const float*)d_in[2];
    const float* W1    = (const float*)d_in[3];
    const float* Wres1 = (const float*)d_in[4];
    const float* g0    = (const float*)d_in[5];
    const float* b0    = (const float*)d_in[6];
    const float* g1    = (const float*)d_in[7];
    const float* b1    = (const float*)d_in[8];
    const float* ew0   = (const float*)d_in[9];
    const float* ew1   = (const float*)d_in[10];
    const int*   row0  = (const int*)d_in[11];
    const int*   col0  = (const int*)d_in[12];
    const int*   row1  = (const int*)d_in[13];
    const int*   col1  = (const int*)d_in[14];
    float* out = (float*)d_out;

    const int D0 = 256, D1 = 512;
    const int N0 = in_sizes[0] / D0;
    const int N1 = in_sizes[1] / D1;
    const int E  = in_sizes[9];

    __half *hproj0, *hproj1, *w0, *w1, *wr;
    float *res1;
    int *cnt0, *cnt1, *off0, *off1, *cur0, *cur1, *bsum;
    int2 *edge0, *edge1;
    cudaGetSymbolAddress((void**)&hproj0, g_hproj0);
    cudaGetSymbolAddress((void**)&hproj1, g_hproj1);
    cudaGetSymbolAddress((void**)&res1,   g_res1);
    cudaGetSymbolAddress((void**)&cnt0,   g_cnt0);
    cudaGetSymbolAddress((void**)&cnt1,   g_cnt1);
    cudaGetSymbolAddress((void**)&off0,   g_off0);
    cudaGetSymbolAddress((void**)&off1,   g_off1);
    cudaGetSymbolAddress((void**)&cur0,   g_cur0);
    cudaGetSymbolAddress((void**)&cur1,   g_cur1);
    cudaGetSymbolAddress((void**)&bsum,   g_bsum);
    cudaGetSymbolAddress((void**)&edge0,  g_edge0);
    cudaGetSymbolAddress((void**)&edge1,  g_edge1);
    cudaGetSymbolAddress((void**)&w0,     g_w0);
    cudaGetSymbolAddress((void**)&w1,     g_w1);
    cudaGetSymbolAddress((void**)&wr,     g_wr);

    // K1: W prep + zero counts
    {
        dim3 g((256 * 512 + 255) / 256, 4);
        prep_kernel<<<g, 256>>>(W0, W1, Wres1, w0, w1, wr, cnt0, cnt1,
                                (N0 > N1 ? N0 : N1));
    }
    // K2: histogram
    {
        dim3 g((E + 255) / 256, 2);
        hist2_kernel<<<g, 256>>>(row0, cnt0, row1, cnt1, E);
    }
    // K3: scan
    {
        const int nblk = (N0 + 255) / 256;
        dim3 g(nblk, 2);
        block_sums_kernel<<<g, 256>>>(cnt0, cnt1, N0, bsum);
        scan_tops_kernel<<<2, 256>>>(bsum, nblk);
        scan_final_kernel<<<g, 256>>>(cnt0, cnt1, N0, bsum,
                                      off0, cur0, off1, cur1);
    }
    // K4: gemm0 (512t, N-tile 128) + scatter both
    {
        constexpr int SMEM1 = 2 * (10240 * 2);          // 40960
        cudaFuncSetAttribute(mega1_kernel,
                             cudaFuncAttributeMaxDynamicSharedMemorySize, SMEM1);
        const int gemm_blocks = 2 * ((N0 + 127) / 128);
        const int per = (E + 511) / 512;
        mega1_kernel<<<gemm_blocks + 2 * per, 512, SMEM1>>>(
            x0, w0, hproj0, N0,
            row0, col0, ew0, cur0, edge0,
            row1, col1, ew1, cur1, edge1, E, gemm_blocks);
    }
    // K5: gemm1 (512t, N-tile 128, dual output)
    {
        constexpr int SMEM2 = 2 * (10240 * 3);          // 61440
        cudaFuncSetAttribute(gemm2_kernel,
                             cudaFuncAttributeMaxDynamicSharedMemorySize, SMEM2);
        dim3 grid(2, (N1 + 127) / 128);
        gemm2_kernel<<<grid, 512, SMEM2>>>(x1, w1, wr, hproj1, res1, N1);
    }
    // K6: aggregate + layernorm (both graphs)
    {
        dim3 g((N0 + 7) / 8, 2);
        aggregate_ln_kernel<<<g, 256>>>(hproj0, x0,   off0, cnt0, edge0, g0, b0,
                                        hproj1, res1, off1, cnt1, edge1, g1, b1,
                                        out, N0);
    }
}